// round 1
// baseline (speedup 1.0000x reference)
#include <cuda_runtime.h>
#include <math.h>

#define Bb 2
#define Cc 320
#define Nn 1024
#define NHh 8
#define DHh 40
#define Ll 2
#define EPS 1e-5f
#define EDGE_SCALE 0.17677669529663687f  /* 32^-0.5 */
#define ATT_SCALE  0.15811388300841897f  /* 40^-0.5 */

// ---------------- scratch (device globals; no allocation allowed) ----------
__device__ float g_node[Bb * Nn * Cc];          // [B,N,C]
__device__ float g_qk2[Bb * Nn * 2 * Cc];       // [B,N,640] (qe | ke)
__device__ float g_edge[Bb * Nn * Nn];          // [B,N,N]
__device__ float g_s[Bb * Cc];                  // [B,C]
__device__ float g_y[Bb * Nn * Cc];             // [B,N,C]
__device__ float g_qkv[Bb * Nn * 3 * Cc];       // [B,N,960]
__device__ float g_attn[Bb * NHh * Nn * Nn];    // [B,H,N,N] 64MB
__device__ float g_wsum[Bb * Nn];               // [B,N]
__device__ float g_nodeout[Bb * Nn * Cc];       // [B,N,C]

// ---------------- block reductions ----------------
__device__ __forceinline__ float blockReduceMax(float v, float* sred) {
    #pragma unroll
    for (int o = 16; o > 0; o >>= 1) v = fmaxf(v, __shfl_xor_sync(0xffffffffu, v, o));
    int w = threadIdx.x >> 5;
    if ((threadIdx.x & 31) == 0) sred[w] = v;
    __syncthreads();
    int nw = blockDim.x >> 5;
    if (threadIdx.x < 32) {
        float x = (threadIdx.x < nw) ? sred[threadIdx.x] : -INFINITY;
        #pragma unroll
        for (int o = 16; o > 0; o >>= 1) x = fmaxf(x, __shfl_xor_sync(0xffffffffu, x, o));
        if (threadIdx.x == 0) sred[0] = x;
    }
    __syncthreads();
    float r = sred[0];
    __syncthreads();
    return r;
}

__device__ __forceinline__ float blockReduceSum(float v, float* sred) {
    #pragma unroll
    for (int o = 16; o > 0; o >>= 1) v += __shfl_xor_sync(0xffffffffu, v, o);
    int w = threadIdx.x >> 5;
    if ((threadIdx.x & 31) == 0) sred[w] = v;
    __syncthreads();
    int nw = blockDim.x >> 5;
    if (threadIdx.x < 32) {
        float x = (threadIdx.x < nw) ? sred[threadIdx.x] : 0.f;
        #pragma unroll
        for (int o = 16; o > 0; o >>= 1) x += __shfl_xor_sync(0xffffffffu, x, o);
        if (threadIdx.x == 0) sred[0] = x;
    }
    __syncthreads();
    float r = sred[0];
    __syncthreads();
    return r;
}

// ---------------- transposes ----------------
__global__ void transpose_in(const float* __restrict__ x) {
    __shared__ float tile[32][33];
    int b = blockIdx.z;
    int c0 = blockIdx.y * 32, n0 = blockIdx.x * 32;
    int tx = threadIdx.x, ty = threadIdx.y;
    tile[ty][tx] = x[(long)b * Cc * Nn + (long)(c0 + ty) * Nn + n0 + tx];
    __syncthreads();
    g_node[((long)b * Nn + n0 + ty) * Cc + c0 + tx] = tile[tx][ty];
}

__global__ void transpose_out(float* __restrict__ out) {
    __shared__ float tile[32][33];
    int b = blockIdx.z;
    int c0 = blockIdx.y * 32, n0 = blockIdx.x * 32;
    int tx = threadIdx.x, ty = threadIdx.y;
    tile[ty][tx] = g_node[((long)b * Nn + n0 + ty) * Cc + c0 + tx];
    __syncthreads();
    out[(long)b * Cc * Nn + (long)(c0 + ty) * Nn + n0 + tx] = tile[tx][ty];
}

// ---------------- generic NT GEMM: C[m,n] = alpha * sum_k A[m,k] W[n,k] + bias[n]
__global__ void gemm_nt(const float* __restrict__ A, const float* __restrict__ W,
                        const float* __restrict__ bias, float* __restrict__ C,
                        int M, int Nc, int K, int lda, int ldw, int ldc,
                        long sA, long sW, long sC, float alpha) {
    __shared__ float As[16][68];
    __shared__ float Ws[16][68];
    int z = blockIdx.z;
    A += (long)z * sA; W += (long)z * sW; C += (long)z * sC;
    int tid = threadIdx.x;
    int tx = tid & 15, ty = tid >> 4;
    int bm = blockIdx.y * 64, bn = blockIdx.x * 64;
    float acc[4][4] = {};
    for (int k0 = 0; k0 < K; k0 += 16) {
        #pragma unroll
        for (int i = 0; i < 4; i++) {
            int idx = tid + i * 256;
            int m = idx >> 4, k = idx & 15;
            As[k][m] = A[(long)(bm + m) * lda + k0 + k];
            Ws[k][m] = W[(long)(bn + m) * ldw + k0 + k];
        }
        __syncthreads();
        #pragma unroll
        for (int k = 0; k < 16; k++) {
            float a[4], w[4];
            #pragma unroll
            for (int i = 0; i < 4; i++) a[i] = As[k][ty * 4 + i];
            #pragma unroll
            for (int j = 0; j < 4; j++) w[j] = Ws[k][tx * 4 + j];
            #pragma unroll
            for (int i = 0; i < 4; i++)
                #pragma unroll
                for (int j = 0; j < 4; j++) acc[i][j] += a[i] * w[j];
        }
        __syncthreads();
    }
    #pragma unroll
    for (int i = 0; i < 4; i++) {
        int m = bm + ty * 4 + i;
        #pragma unroll
        for (int j = 0; j < 4; j++) {
            int n = bn + tx * 4 + j;
            float v = acc[i][j] * alpha;
            if (bias) v += bias[n];
            C[(long)m * ldc + n] = v;
        }
    }
}

// ---------------- row softmax (in-place) for edge [B*N rows of 1024] -------
__global__ void edge_softmax(void) {
    __shared__ float sred[32];
    long row = blockIdx.x;
    float* p = g_edge + row * Nn;
    int tid = threadIdx.x;
    float r[4];
    float lmax = -INFINITY;
    #pragma unroll
    for (int i = 0; i < 4; i++) { r[i] = p[tid + i * 256]; lmax = fmaxf(lmax, r[i]); }
    float smax = blockReduceMax(lmax, sred);
    float lsum = 0.f;
    #pragma unroll
    for (int i = 0; i < 4; i++) { r[i] = __expf(r[i] - smax); lsum += r[i]; }
    float Z = blockReduceSum(lsum, sred);
    float inv = 1.f / Z;
    #pragma unroll
    for (int i = 0; i < 4; i++) p[tid + i * 256] = r[i] * inv;
}

// ---------------- fc_prior: s[b,c] --------------------------------------
__global__ void fcp_kernel(const float* __restrict__ da, const float* __restrict__ fw,
                           const float* __restrict__ fb) {
    __shared__ float t[64];
    int b = blockIdx.x;
    int tid = threadIdx.x;  // 320
    if (tid < 64) {
        float s = 0.f;
        #pragma unroll
        for (int a = 0; a < 16; a++) s += da[(long)b * 16 * 64 + a * 64 + tid];
        t[tid] = s;
    }
    __syncthreads();
    float s = 16.f * fb[tid];
    #pragma unroll
    for (int e = 0; e < 64; e++) s += t[e] * fw[tid * 64 + e];
    g_s[b * Cc + tid] = s;
}

// ---------------- LN1 -> gate -> LN2 ------------------------------------
__global__ void norm_kernel(const float* __restrict__ g1, const float* __restrict__ b1,
                            const float* __restrict__ g2, const float* __restrict__ b2) {
    __shared__ float sred[32];
    int bn = blockIdx.x;
    int b = bn >> 10, n = bn & 1023;
    int c = threadIdx.x;  // 320
    float x = g_node[(long)bn * Cc + c];
    float mean = blockReduceSum(x, sred) * (1.f / Cc);
    float d = x - mean;
    float var = blockReduceSum(d * d, sred) * (1.f / Cc);
    float nt = d * rsqrtf(var + EPS) * g1[c] + b1[c];
    float diag = g_edge[(long)b * Nn * Nn + (long)n * Nn + n];
    float v2 = diag * nt * g_s[b * Cc + c] + nt;
    float mean2 = blockReduceSum(v2, sred) * (1.f / Cc);
    float dd = v2 - mean2;
    float var2 = blockReduceSum(dd * dd, sred) * (1.f / Cc);
    g_y[(long)bn * Cc + c] = dd * rsqrtf(var2 + EPS) * g2[c] + b2[c];
}

// ---------------- attn scores: S = QK^T*scale + edge*ew + eb --------------
__global__ void attn_score(const float* __restrict__ exp_w, const float* __restrict__ exp_b) {
    __shared__ float Qs[64][41];
    __shared__ float Ks[64][41];
    int bh = blockIdx.z;
    int b = bh >> 3, h = bh & 7;
    int n0 = blockIdx.y * 64, m0 = blockIdx.x * 64;
    const float* Qb = g_qkv + (long)b * Nn * 960 + h * DHh;
    const float* Kb = g_qkv + (long)b * Nn * 960 + Cc + h * DHh;
    int tid = threadIdx.x;
    for (int idx = tid; idx < 64 * 40; idx += 256) {
        int r = idx / 40, k = idx % 40;
        Qs[r][k] = Qb[(long)(n0 + r) * 960 + k];
        Ks[r][k] = Kb[(long)(m0 + r) * 960 + k];
    }
    __syncthreads();
    int tx = tid & 15, ty = tid >> 4;
    float acc[4][4] = {};
    #pragma unroll
    for (int k = 0; k < 40; k++) {
        float a[4], kk[4];
        #pragma unroll
        for (int i = 0; i < 4; i++) a[i] = Qs[ty * 4 + i][k];
        #pragma unroll
        for (int j = 0; j < 4; j++) kk[j] = Ks[tx * 4 + j][k];
        #pragma unroll
        for (int i = 0; i < 4; i++)
            #pragma unroll
            for (int j = 0; j < 4; j++) acc[i][j] += a[i] * kk[j];
    }
    float ew = exp_w[h], eb = exp_b[h];
    #pragma unroll
    for (int i = 0; i < 4; i++) {
        int n = n0 + ty * 4 + i;
        #pragma unroll
        for (int j = 0; j < 4; j++) {
            int m = m0 + tx * 4 + j;
            float e = g_edge[(long)b * Nn * Nn + (long)n * Nn + m];
            g_attn[(((long)b * NHh + h) * Nn + n) * Nn + m] = acc[i][j] * ATT_SCALE + e * ew + eb;
        }
    }
}

// ---------------- per-(b,n): head softmax, edge_new, ws softmax, edge update
__global__ void softmax_ednew(const float* __restrict__ red_w, const float* __restrict__ red_b) {
    __shared__ float sred[32];
    int bn = blockIdx.x;
    int b = bn >> 10, n = bn & 1023;
    int tid = threadIdx.x;  // 256, each owns cols tid+{0,256,512,768}
    float edreg[4] = {0.f, 0.f, 0.f, 0.f};
    for (int h = 0; h < NHh; h++) {
        float* Ab = g_attn + (((long)b * NHh + h) * Nn + n) * Nn;
        float r[4];
        float lmax = -INFINITY;
        #pragma unroll
        for (int i = 0; i < 4; i++) { r[i] = Ab[tid + i * 256]; lmax = fmaxf(lmax, r[i]); }
        float smax = blockReduceMax(lmax, sred);
        float lsum = 0.f;
        float e[4];
        #pragma unroll
        for (int i = 0; i < 4; i++) { e[i] = __expf(r[i] - smax); lsum += e[i]; }
        float Z = blockReduceSum(lsum, sred);
        float inv = 1.f / Z;
        float rw = red_w[h];
        #pragma unroll
        for (int i = 0; i < 4; i++) {
            float a = e[i] * inv;
            Ab[tid + i * 256] = a;          // overwrite score with prob for AV
            edreg[i] += rw * (a + r[i]);
        }
    }
    float rb = red_b[0];
    #pragma unroll
    for (int i = 0; i < 4; i++) edreg[i] += rb;
    // ws = softmax(edge_new); wsum = sum(ws * edge_new)
    float lmax = -INFINITY;
    #pragma unroll
    for (int i = 0; i < 4; i++) lmax = fmaxf(lmax, edreg[i]);
    float M2 = blockReduceMax(lmax, sred);
    float lsum = 0.f;
    #pragma unroll
    for (int i = 0; i < 4; i++) lsum += __expf(edreg[i] - M2);
    float Z2 = blockReduceSum(lsum, sred);
    float invZ2 = 1.f / Z2;
    float lws = 0.f;
    #pragma unroll
    for (int i = 0; i < 4; i++) lws += __expf(edreg[i] - M2) * invZ2 * edreg[i];
    float wsum = blockReduceSum(lws, sred);
    if (tid == 0) g_wsum[bn] = wsum;
    float* ep = g_edge + (long)b * Nn * Nn + (long)n * Nn;
    #pragma unroll
    for (int i = 0; i < 4; i++) ep[tid + i * 256] += edreg[i];
}

// ---------------- AV: node_out[b,n,h*40+d] = sum_m a*v + wsum -------------
__global__ void av_kernel(void) {
    __shared__ float As[64][33];
    __shared__ float Vs[32][41];
    int bh = blockIdx.y;
    int b = bh >> 3, h = bh & 7;
    int n0 = blockIdx.x * 64;
    int tid = threadIdx.x;
    int row = tid >> 2;   // 0..63
    int dg = tid & 3;     // 0..3 (10 cols each)
    float acc[10] = {};
    const float* Ab = g_attn + ((long)b * NHh + h) * Nn * Nn;
    const float* Vb = g_qkv + (long)b * Nn * 960 + 2 * Cc + h * DHh;
    for (int m0 = 0; m0 < Nn; m0 += 32) {
        for (int idx = tid; idx < 64 * 32; idx += 256) {
            int r = idx >> 5, mm = idx & 31;
            As[r][mm] = Ab[(long)(n0 + r) * Nn + m0 + mm];
        }
        for (int idx = tid; idx < 32 * 40; idx += 256) {
            int mm = idx / 40, d = idx % 40;
            Vs[mm][d] = Vb[(long)(m0 + mm) * 960 + d];
        }
        __syncthreads();
        #pragma unroll
        for (int mm = 0; mm < 32; mm++) {
            float a = As[row][mm];
            #pragma unroll
            for (int j = 0; j < 10; j++) acc[j] += a * Vs[mm][dg * 10 + j];
        }
        __syncthreads();
    }
    int n = n0 + row;
    float w = g_wsum[b * Nn + n];
    #pragma unroll
    for (int j = 0; j < 10; j++)
        g_nodeout[((long)b * Nn + n) * Cc + h * DHh + dg * 10 + j] = acc[j] + w;
}

// ---------------- host ----------------
static float* sym(const void* s) {
    void* p = nullptr;
    cudaGetSymbolAddress(&p, s);
    return (float*)p;
}

extern "C" void kernel_launch(void* const* d_in, const int* in_sizes, int n_in,
                              void* d_out, int out_size) {
    const float* x        = (const float*)d_in[0];
    const float* da_prior = (const float*)d_in[1];
    const float* qk_w     = (const float*)d_in[2];
    const float* fcp_w    = (const float*)d_in[3];
    const float* fcp_b    = (const float*)d_in[4];
    const float* ln1_g    = (const float*)d_in[5];
    const float* ln1_b    = (const float*)d_in[6];
    const float* gln_g    = (const float*)d_in[7];
    const float* gln_b    = (const float*)d_in[8];
    const float* qkv_w    = (const float*)d_in[9];
    const float* qkv_b    = (const float*)d_in[10];
    const float* proj_w   = (const float*)d_in[11];
    const float* proj_b   = (const float*)d_in[12];
    const float* exp_w    = (const float*)d_in[13];
    const float* exp_b    = (const float*)d_in[14];
    const float* red_w    = (const float*)d_in[15];
    const float* red_b    = (const float*)d_in[16];
    float* out = (float*)d_out;

    float* p_node    = sym(g_node);
    float* p_qk2     = sym(g_qk2);
    float* p_edge    = sym(g_edge);
    float* p_y       = sym(g_y);
    float* p_qkv     = sym(g_qkv);
    float* p_nodeout = sym(g_nodeout);

    // x [B,C,N] -> node [B,N,C]
    transpose_in<<<dim3(32, 10, Bb), dim3(32, 32)>>>(x);

    // qe|ke = node @ qk_w^T   [2048,640]
    gemm_nt<<<dim3(10, 32, 1), 256>>>(p_node, qk_w, nullptr, p_qk2,
                                      Bb * Nn, 2 * Cc, Cc, Cc, Cc, 2 * Cc,
                                      0, 0, 0, 1.f);
    // edge scores = qe @ ke^T * EDGE_SCALE   per batch
    gemm_nt<<<dim3(16, 16, Bb), 256>>>(p_qk2, p_qk2 + Cc, nullptr, p_edge,
                                       Nn, Nn, Cc, 2 * Cc, 2 * Cc, Nn,
                                       (long)Nn * 2 * Cc, (long)Nn * 2 * Cc, (long)Nn * Nn,
                                       EDGE_SCALE);
    edge_softmax<<<Bb * Nn, 256>>>();
    fcp_kernel<<<Bb, Cc>>>(da_prior, fcp_w, fcp_b);

    for (int l = 0; l < Ll; l++) {
        norm_kernel<<<Bb * Nn, Cc>>>(ln1_g + l * Cc, ln1_b + l * Cc,
                                     gln_g + l * Cc, gln_b + l * Cc);
        gemm_nt<<<dim3(15, 32, 1), 256>>>(p_y, qkv_w + (long)l * 3 * Cc * Cc,
                                          qkv_b + l * 3 * Cc, p_qkv,
                                          Bb * Nn, 3 * Cc, Cc, Cc, Cc, 3 * Cc,
                                          0, 0, 0, 1.f);
        attn_score<<<dim3(16, 16, Bb * NHh), 256>>>(exp_w + l * NHh, exp_b + l * NHh);
        softmax_ednew<<<Bb * Nn, 256>>>(red_w + l * NHh, red_b + l);
        av_kernel<<<dim3(16, Bb * NHh), 256>>>();
        gemm_nt<<<dim3(5, 32, 1), 256>>>(p_nodeout, proj_w + (long)l * Cc * Cc,
                                         proj_b + l * Cc, p_node,
                                         Bb * Nn, Cc, Cc, Cc, Cc, Cc,
                                         0, 0, 0, 1.f);
    }

    // node [B,N,C] -> out [B,C,N]
    transpose_out<<<dim3(32, 10, Bb), dim3(32, 32)>>>(out);
}

// round 2
// speedup vs baseline: 1.7991x; 1.7991x over previous
#include <cuda_runtime.h>
#include <mma.h>
#include <math.h>

using namespace nvcuda;

#define Bb 2
#define Cc 320
#define Nn 1024
#define NHh 8
#define DHh 40
#define Ll 2
#define EPS 1e-5f
#define EDGE_SCALE 0.17677669529663687f  /* 32^-0.5 */
#define ATT_SCALE  0.15811388300841897f  /* 40^-0.5 */

// ---------------- scratch (device globals; no allocation allowed) ----------
__device__ float g_node[Bb * Nn * Cc];          // [B,N,C]
__device__ float g_qk2[Bb * Nn * 2 * Cc];       // [B,N,640] (qe | ke)
__device__ float g_edge[Bb * Nn * Nn];          // [B,N,N]
__device__ float g_s[Bb * Cc];                  // [B,C]
__device__ float g_y[Bb * Nn * Cc];             // [B,N,C]
__device__ float g_qkv[Bb * Nn * 3 * Cc];       // [B,N,960]
__device__ float g_attn[Bb * NHh * Nn * Nn];    // [B,H,N,N] 64MB
__device__ float g_wsum[Bb * Nn];               // [B,N]
__device__ float g_nodeout[Bb * Nn * Cc];       // [B,N,C]

// ---------------- block reductions ----------------
__device__ __forceinline__ float blockReduceMax(float v, float* sred) {
    #pragma unroll
    for (int o = 16; o > 0; o >>= 1) v = fmaxf(v, __shfl_xor_sync(0xffffffffu, v, o));
    int w = threadIdx.x >> 5;
    if ((threadIdx.x & 31) == 0) sred[w] = v;
    __syncthreads();
    int nw = blockDim.x >> 5;
    if (threadIdx.x < 32) {
        float x = (threadIdx.x < nw) ? sred[threadIdx.x] : -INFINITY;
        #pragma unroll
        for (int o = 16; o > 0; o >>= 1) x = fmaxf(x, __shfl_xor_sync(0xffffffffu, x, o));
        if (threadIdx.x == 0) sred[0] = x;
    }
    __syncthreads();
    float r = sred[0];
    __syncthreads();
    return r;
}

__device__ __forceinline__ float blockReduceSum(float v, float* sred) {
    #pragma unroll
    for (int o = 16; o > 0; o >>= 1) v += __shfl_xor_sync(0xffffffffu, v, o);
    int w = threadIdx.x >> 5;
    if ((threadIdx.x & 31) == 0) sred[w] = v;
    __syncthreads();
    int nw = blockDim.x >> 5;
    if (threadIdx.x < 32) {
        float x = (threadIdx.x < nw) ? sred[threadIdx.x] : 0.f;
        #pragma unroll
        for (int o = 16; o > 0; o >>= 1) x += __shfl_xor_sync(0xffffffffu, x, o);
        if (threadIdx.x == 0) sred[0] = x;
    }
    __syncthreads();
    float r = sred[0];
    __syncthreads();
    return r;
}

// ---------------- transposes ----------------
__global__ void transpose_in(const float* __restrict__ x) {
    __shared__ float tile[32][33];
    int b = blockIdx.z;
    int c0 = blockIdx.y * 32, n0 = blockIdx.x * 32;
    int tx = threadIdx.x, ty = threadIdx.y;
    tile[ty][tx] = x[(long)b * Cc * Nn + (long)(c0 + ty) * Nn + n0 + tx];
    __syncthreads();
    g_node[((long)b * Nn + n0 + ty) * Cc + c0 + tx] = tile[tx][ty];
}

__global__ void transpose_out(float* __restrict__ out) {
    __shared__ float tile[32][33];
    int b = blockIdx.z;
    int c0 = blockIdx.y * 32, n0 = blockIdx.x * 32;
    int tx = threadIdx.x, ty = threadIdx.y;
    tile[ty][tx] = g_node[((long)b * Nn + n0 + ty) * Cc + c0 + tx];
    __syncthreads();
    out[(long)b * Cc * Nn + (long)(c0 + ty) * Nn + n0 + tx] = tile[tx][ty];
}

// ---------------- TF32 WMMA NT GEMM: C[m,n] = alpha*sum_k A[m,k]W[n,k] + bias[n]
// Block tile 128x64, K-tile 32. 256 threads = 8 warps in 4x2, warp tile 32x32.
__global__ void gemm_tf32(const float* __restrict__ A, const float* __restrict__ W,
                          const float* __restrict__ bias, float* __restrict__ C,
                          int M, int Ncols, int K, int lda, int ldw, int ldc,
                          long sA, long sW, long sC, float alpha) {
    __shared__ float sbuf[8704];  // As[128][36] | Ws[64][36]; reused as Cs[128][68]
    float (*As)[36] = (float(*)[36])sbuf;
    float (*Ws)[36] = (float(*)[36])(sbuf + 128 * 36);
    int z = blockIdx.z;
    A += (long)z * sA; W += (long)z * sW; C += (long)z * sC;
    int bm = blockIdx.y * 128, bn = blockIdx.x * 64;
    int tid = threadIdx.x;
    int w = tid >> 5;
    int wm = w >> 1, wn = w & 1;

    wmma::fragment<wmma::accumulator, 16, 16, 8, float> c[2][2];
    #pragma unroll
    for (int i = 0; i < 2; i++)
        #pragma unroll
        for (int j = 0; j < 2; j++) wmma::fill_fragment(c[i][j], 0.f);

    for (int k0 = 0; k0 < K; k0 += 32) {
        #pragma unroll
        for (int i = 0; i < 4; i++) {  // A: 128x32 = 1024 float4
            int idx = tid + i * 256;
            int r = idx >> 3, c4 = (idx & 7) * 4;
            *(float4*)&As[r][c4] = *(const float4*)&A[(long)(bm + r) * lda + k0 + c4];
        }
        #pragma unroll
        for (int i = 0; i < 2; i++) {  // W: 64x32 = 512 float4
            int idx = tid + i * 256;
            int r = idx >> 3, c4 = (idx & 7) * 4;
            *(float4*)&Ws[r][c4] = *(const float4*)&W[(long)(bn + r) * ldw + k0 + c4];
        }
        __syncthreads();
        #pragma unroll
        for (int kk = 0; kk < 4; kk++) {
            wmma::fragment<wmma::matrix_a, 16, 16, 8, wmma::precision::tf32, wmma::row_major> a[2];
            wmma::fragment<wmma::matrix_b, 16, 16, 8, wmma::precision::tf32, wmma::col_major> bf[2];
            #pragma unroll
            for (int i = 0; i < 2; i++) {
                wmma::load_matrix_sync(a[i], &As[wm * 32 + i * 16][kk * 8], 36);
                #pragma unroll
                for (int e = 0; e < a[i].num_elements; e++) a[i].x[e] = wmma::__float_to_tf32(a[i].x[e]);
            }
            #pragma unroll
            for (int j = 0; j < 2; j++) {
                wmma::load_matrix_sync(bf[j], &Ws[wn * 32 + j * 16][kk * 8], 36);
                #pragma unroll
                for (int e = 0; e < bf[j].num_elements; e++) bf[j].x[e] = wmma::__float_to_tf32(bf[j].x[e]);
            }
            #pragma unroll
            for (int i = 0; i < 2; i++)
                #pragma unroll
                for (int j = 0; j < 2; j++) wmma::mma_sync(c[i][j], a[i], bf[j], c[i][j]);
        }
        __syncthreads();
    }
    // epilogue via smem roundtrip
    #pragma unroll
    for (int i = 0; i < 2; i++)
        #pragma unroll
        for (int j = 0; j < 2; j++) {
            #pragma unroll
            for (int e = 0; e < c[i][j].num_elements; e++) c[i][j].x[e] *= alpha;
            wmma::store_matrix_sync(&sbuf[(wm * 32 + i * 16) * 68 + wn * 32 + j * 16],
                                    c[i][j], 68, wmma::mem_row_major);
        }
    __syncthreads();
    #pragma unroll
    for (int i = 0; i < 8; i++) {  // 128x64 = 2048 float4
        int idx = tid + i * 256;
        int r = idx >> 4, c4 = (idx & 15) * 4;
        float4 v = *(float4*)&sbuf[r * 68 + c4];
        if (bias) {
            float4 bb = *(const float4*)&bias[bn + c4];
            v.x += bb.x; v.y += bb.y; v.z += bb.z; v.w += bb.w;
        }
        *(float4*)&C[(long)(bm + r) * ldc + bn + c4] = v;
    }
}

// ---------------- row softmax (in-place) for edge [B*N rows of 1024] -------
__global__ void edge_softmax(void) {
    __shared__ float sred[32];
    long row = blockIdx.x;
    float* p = g_edge + row * Nn;
    int tid = threadIdx.x;
    float r[4];
    float lmax = -INFINITY;
    #pragma unroll
    for (int i = 0; i < 4; i++) { r[i] = p[tid + i * 256]; lmax = fmaxf(lmax, r[i]); }
    float smax = blockReduceMax(lmax, sred);
    float lsum = 0.f;
    #pragma unroll
    for (int i = 0; i < 4; i++) { r[i] = __expf(r[i] - smax); lsum += r[i]; }
    float Z = blockReduceSum(lsum, sred);
    float inv = 1.f / Z;
    #pragma unroll
    for (int i = 0; i < 4; i++) p[tid + i * 256] = r[i] * inv;
}

// ---------------- fc_prior: s[b,c] --------------------------------------
__global__ void fcp_kernel(const float* __restrict__ da, const float* __restrict__ fw,
                           const float* __restrict__ fb) {
    __shared__ float t[64];
    int b = blockIdx.x;
    int tid = threadIdx.x;  // 320
    if (tid < 64) {
        float s = 0.f;
        #pragma unroll
        for (int a = 0; a < 16; a++) s += da[(long)b * 16 * 64 + a * 64 + tid];
        t[tid] = s;
    }
    __syncthreads();
    float s = 16.f * fb[tid];
    #pragma unroll
    for (int e = 0; e < 64; e++) s += t[e] * fw[tid * 64 + e];
    g_s[b * Cc + tid] = s;
}

// ---------------- LN1 -> gate -> LN2 ------------------------------------
__global__ void norm_kernel(const float* __restrict__ g1, const float* __restrict__ b1,
                            const float* __restrict__ g2, const float* __restrict__ b2) {
    __shared__ float sred[32];
    int bn = blockIdx.x;
    int b = bn >> 10, n = bn & 1023;
    int c = threadIdx.x;  // 320
    float x = g_node[(long)bn * Cc + c];
    float mean = blockReduceSum(x, sred) * (1.f / Cc);
    float d = x - mean;
    float var = blockReduceSum(d * d, sred) * (1.f / Cc);
    float nt = d * rsqrtf(var + EPS) * g1[c] + b1[c];
    float diag = g_edge[(long)b * Nn * Nn + (long)n * Nn + n];
    float v2 = diag * nt * g_s[b * Cc + c] + nt;
    float mean2 = blockReduceSum(v2, sred) * (1.f / Cc);
    float dd = v2 - mean2;
    float var2 = blockReduceSum(dd * dd, sred) * (1.f / Cc);
    g_y[(long)bn * Cc + c] = dd * rsqrtf(var2 + EPS) * g2[c] + b2[c];
}

// ---------------- attn scores (TF32 WMMA): S = QK^T*scale + edge*ew + eb ---
// Block 64x64 tile, 8 warps 4x2, warp tile 16x32.
__global__ void attn_score_tf32(const float* __restrict__ exp_w, const float* __restrict__ exp_b) {
    __shared__ float sb[5632];  // Qs[64][44] | Ks[64][44]; reused as Cs[64][68]
    float (*Qs)[44] = (float(*)[44])sb;
    float (*Ks)[44] = (float(*)[44])(sb + 64 * 44);
    int bh = blockIdx.z;
    int b = bh >> 3, h = bh & 7;
    int n0 = blockIdx.y * 64, m0 = blockIdx.x * 64;
    const float* Qb = g_qkv + (long)b * Nn * 960 + h * DHh;
    const float* Kb = Qb + Cc;
    int tid = threadIdx.x;
    for (int idx = tid; idx < 640; idx += 256) {
        int r = idx / 10, c4 = (idx % 10) * 4;
        *(float4*)&Qs[r][c4] = *(const float4*)&Qb[(long)(n0 + r) * 960 + c4];
        *(float4*)&Ks[r][c4] = *(const float4*)&Kb[(long)(m0 + r) * 960 + c4];
    }
    __syncthreads();
    int w = tid >> 5, wr = w >> 1, wc = w & 1;
    wmma::fragment<wmma::accumulator, 16, 16, 8, float> c[2];
    wmma::fill_fragment(c[0], 0.f);
    wmma::fill_fragment(c[1], 0.f);
    #pragma unroll
    for (int kk = 0; kk < 5; kk++) {
        wmma::fragment<wmma::matrix_a, 16, 16, 8, wmma::precision::tf32, wmma::row_major> a;
        wmma::load_matrix_sync(a, &Qs[wr * 16][kk * 8], 44);
        #pragma unroll
        for (int e = 0; e < a.num_elements; e++) a.x[e] = wmma::__float_to_tf32(a.x[e]);
        #pragma unroll
        for (int j = 0; j < 2; j++) {
            wmma::fragment<wmma::matrix_b, 16, 16, 8, wmma::precision::tf32, wmma::col_major> bf;
            wmma::load_matrix_sync(bf, &Ks[wc * 32 + j * 16][kk * 8], 44);
            #pragma unroll
            for (int e = 0; e < bf.num_elements; e++) bf.x[e] = wmma::__float_to_tf32(bf.x[e]);
            wmma::mma_sync(c[j], a, bf, c[j]);
        }
    }
    __syncthreads();
    #pragma unroll
    for (int j = 0; j < 2; j++) {
        #pragma unroll
        for (int e = 0; e < c[j].num_elements; e++) c[j].x[e] *= ATT_SCALE;
        wmma::store_matrix_sync(&sb[(wr * 16) * 68 + wc * 32 + j * 16], c[j], 68,
                                wmma::mem_row_major);
    }
    __syncthreads();
    float ew = exp_w[h], eb = exp_b[h];
    const float* ep = g_edge + (long)b * Nn * Nn;
    float* op = g_attn + ((long)b * NHh + h) * Nn * Nn;
    #pragma unroll
    for (int i = 0; i < 4; i++) {  // 64x64 = 1024 float4
        int idx = tid + i * 256;
        int r = idx >> 4, c4 = (idx & 15) * 4;
        float4 s = *(float4*)&sb[r * 68 + c4];
        float4 e = *(const float4*)&ep[(long)(n0 + r) * Nn + m0 + c4];
        s.x += e.x * ew + eb; s.y += e.y * ew + eb;
        s.z += e.z * ew + eb; s.w += e.w * ew + eb;
        *(float4*)&op[(long)(n0 + r) * Nn + m0 + c4] = s;
    }
}

// ---------------- per-(b,n): head softmax, edge_new, ws softmax, edge update
__global__ void softmax_ednew(const float* __restrict__ red_w, const float* __restrict__ red_b) {
    __shared__ float sred[32];
    int bn = blockIdx.x;
    int b = bn >> 10, n = bn & 1023;
    int tid = threadIdx.x;  // 256
    float edreg[4] = {0.f, 0.f, 0.f, 0.f};
    for (int h = 0; h < NHh; h++) {
        float* Ab = g_attn + (((long)b * NHh + h) * Nn + n) * Nn;
        float r[4];
        float lmax = -INFINITY;
        #pragma unroll
        for (int i = 0; i < 4; i++) { r[i] = Ab[tid + i * 256]; lmax = fmaxf(lmax, r[i]); }
        float smax = blockReduceMax(lmax, sred);
        float lsum = 0.f;
        float e[4];
        #pragma unroll
        for (int i = 0; i < 4; i++) { e[i] = __expf(r[i] - smax); lsum += e[i]; }
        float Z = blockReduceSum(lsum, sred);
        float inv = 1.f / Z;
        float rw = red_w[h];
        #pragma unroll
        for (int i = 0; i < 4; i++) {
            float a = e[i] * inv;
            Ab[tid + i * 256] = a;          // overwrite score with prob for AV
            edreg[i] += rw * (a + r[i]);
        }
    }
    float rb = red_b[0];
    #pragma unroll
    for (int i = 0; i < 4; i++) edreg[i] += rb;
    float lmax = -INFINITY;
    #pragma unroll
    for (int i = 0; i < 4; i++) lmax = fmaxf(lmax, edreg[i]);
    float M2 = blockReduceMax(lmax, sred);
    float lsum = 0.f;
    #pragma unroll
    for (int i = 0; i < 4; i++) lsum += __expf(edreg[i] - M2);
    float Z2 = blockReduceSum(lsum, sred);
    float invZ2 = 1.f / Z2;
    float lws = 0.f;
    #pragma unroll
    for (int i = 0; i < 4; i++) lws += __expf(edreg[i] - M2) * invZ2 * edreg[i];
    float wsum = blockReduceSum(lws, sred);
    if (tid == 0) g_wsum[bn] = wsum;
    float* ep = g_edge + (long)b * Nn * Nn + (long)n * Nn;
    #pragma unroll
    for (int i = 0; i < 4; i++) ep[tid + i * 256] += edreg[i];
}

// ---------------- AV (TF32 WMMA): node_out = A @ V + wsum ------------------
// Block: 128 rows (8 warps x 16) x 48 cols (d padded 40->48), k-tile 64 over m.
__global__ void av_tf32(void) {
    __shared__ float sb[6144];  // Vs[64][48] (3072) ; reused as Cs[128][48]
    float (*Vs)[48] = (float(*)[48])sb;
    int bh = blockIdx.y;
    int b = bh >> 3, h = bh & 7;
    int n0 = blockIdx.x * 128;
    int tid = threadIdx.x;
    const float* Ab = g_attn + ((long)b * NHh + h) * Nn * Nn;
    const float* Vb = g_qkv + (long)b * Nn * 960 + 2 * Cc + h * DHh;
    // zero pad cols 40..47 (written once, never overwritten)
    for (int idx = tid; idx < 512; idx += 256) Vs[idx >> 3][40 + (idx & 7)] = 0.f;
    int w = tid >> 5;
    wmma::fragment<wmma::accumulator, 16, 16, 8, float> c[3];
    #pragma unroll
    for (int j = 0; j < 3; j++) wmma::fill_fragment(c[j], 0.f);
    for (int m0 = 0; m0 < Nn; m0 += 64) {
        __syncthreads();
        for (int idx = tid; idx < 640; idx += 256) {  // V: 64x40 = 640 f4
            int mm = idx / 10, c4 = (idx % 10) * 4;
            *(float4*)&Vs[mm][c4] = *(const float4*)&Vb[(long)(m0 + mm) * 960 + c4];
        }
        __syncthreads();
        #pragma unroll
        for (int kk = 0; kk < 8; kk++) {
            wmma::fragment<wmma::matrix_a, 16, 16, 8, wmma::precision::tf32, wmma::row_major> a;
            wmma::load_matrix_sync(a, &Ab[(long)(n0 + w * 16) * Nn + m0 + kk * 8], Nn);
            #pragma unroll
            for (int e = 0; e < a.num_elements; e++) a.x[e] = wmma::__float_to_tf32(a.x[e]);
            #pragma unroll
            for (int j = 0; j < 3; j++) {
                wmma::fragment<wmma::matrix_b, 16, 16, 8, wmma::precision::tf32, wmma::row_major> bf;
                wmma::load_matrix_sync(bf, &Vs[kk * 8][j * 16], 48);
                #pragma unroll
                for (int e = 0; e < bf.num_elements; e++) bf.x[e] = wmma::__float_to_tf32(bf.x[e]);
                wmma::mma_sync(c[j], a, bf, c[j]);
            }
        }
    }
    __syncthreads();
    #pragma unroll
    for (int j = 0; j < 3; j++)
        wmma::store_matrix_sync(&sb[(w * 16) * 48 + j * 16], c[j], 48, wmma::mem_row_major);
    __syncthreads();
    const float* wsp = g_wsum + b * Nn + n0;
    float* op = g_nodeout + ((long)b * Nn + n0) * Cc + h * DHh;
    #pragma unroll
    for (int i = 0; i < 5; i++) {  // 128x40 = 1280 f4
        int idx = tid + i * 256;
        int r = idx / 10, c4 = (idx % 10) * 4;
        float wv = wsp[r];
        float4 v = *(float4*)&sb[r * 48 + c4];
        v.x += wv; v.y += wv; v.z += wv; v.w += wv;
        *(float4*)&op[(long)r * Cc + c4] = v;
    }
}

// ---------------- host ----------------
static float* sym(const void* s) {
    void* p = nullptr;
    cudaGetSymbolAddress(&p, s);
    return (float*)p;
}

extern "C" void kernel_launch(void* const* d_in, const int* in_sizes, int n_in,
                              void* d_out, int out_size) {
    const float* x        = (const float*)d_in[0];
    const float* da_prior = (const float*)d_in[1];
    const float* qk_w     = (const float*)d_in[2];
    const float* fcp_w    = (const float*)d_in[3];
    const float* fcp_b    = (const float*)d_in[4];
    const float* ln1_g    = (const float*)d_in[5];
    const float* ln1_b    = (const float*)d_in[6];
    const float* gln_g    = (const float*)d_in[7];
    const float* gln_b    = (const float*)d_in[8];
    const float* qkv_w    = (const float*)d_in[9];
    const float* qkv_b    = (const float*)d_in[10];
    const float* proj_w   = (const float*)d_in[11];
    const float* proj_b   = (const float*)d_in[12];
    const float* exp_w    = (const float*)d_in[13];
    const float* exp_b    = (const float*)d_in[14];
    const float* red_w    = (const float*)d_in[15];
    const float* red_b    = (const float*)d_in[16];
    float* out = (float*)d_out;

    float* p_node    = sym(g_node);
    float* p_qk2     = sym(g_qk2);
    float* p_edge    = sym(g_edge);
    float* p_y       = sym(g_y);
    float* p_qkv     = sym(g_qkv);
    float* p_nodeout = sym(g_nodeout);

    // x [B,C,N] -> node [B,N,C]
    transpose_in<<<dim3(32, 10, Bb), dim3(32, 32)>>>(x);

    // qe|ke = node @ qk_w^T   [2048,640]
    gemm_tf32<<<dim3(10, 16, 1), 256>>>(p_node, qk_w, nullptr, p_qk2,
                                        Bb * Nn, 2 * Cc, Cc, Cc, Cc, 2 * Cc,
                                        0, 0, 0, 1.f);
    // edge scores = qe @ ke^T * EDGE_SCALE   per batch
    gemm_tf32<<<dim3(16, 8, Bb), 256>>>(p_qk2, p_qk2 + Cc, nullptr, p_edge,
                                        Nn, Nn, Cc, 2 * Cc, 2 * Cc, Nn,
                                        (long)Nn * 2 * Cc, (long)Nn * 2 * Cc, (long)Nn * Nn,
                                        EDGE_SCALE);
    edge_softmax<<<Bb * Nn, 256>>>();
    fcp_kernel<<<Bb, Cc>>>(da_prior, fcp_w, fcp_b);

    for (int l = 0; l < Ll; l++) {
        norm_kernel<<<Bb * Nn, Cc>>>(ln1_g + l * Cc, ln1_b + l * Cc,
                                     gln_g + l * Cc, gln_b + l * Cc);
        gemm_tf32<<<dim3(15, 16, 1), 256>>>(p_y, qkv_w + (long)l * 3 * Cc * Cc,
                                            qkv_b + l * 3 * Cc, p_qkv,
                                            Bb * Nn, 3 * Cc, Cc, Cc, Cc, 3 * Cc,
                                            0, 0, 0, 1.f);
        attn_score_tf32<<<dim3(16, 16, Bb * NHh), 256>>>(exp_w + l * NHh, exp_b + l * NHh);
        softmax_ednew<<<Bb * Nn, 256>>>(red_w + l * NHh, red_b + l);
        av_tf32<<<dim3(8, Bb * NHh), 256>>>();
        gemm_tf32<<<dim3(5, 16, 1), 256>>>(p_nodeout, proj_w + (long)l * Cc * Cc,
                                           proj_b + l * Cc, p_node,
                                           Bb * Nn, Cc, Cc, Cc, Cc, Cc,
                                           0, 0, 0, 1.f);
    }

    // node [B,N,C] -> out [B,C,N]
    transpose_out<<<dim3(32, 10, Bb), dim3(32, 32)>>>(out);
}